// round 15
// baseline (speedup 1.0000x reference)
#include <cuda_runtime.h>
#include <cuda_bf16.h>
#include <math.h>
#include <stdint.h>

// ---------------- problem constants ----------------
#define NN      100000
#define EE      1600000
#define ETOT    (EE + NN)        // edges + self loops
#define INDIM   512
#define H1      8
#define HIDDIM  64
#define OUTDIM  64
#define NEG_SLOPE 0.2f
#define CAP     64               // per-node in-edge bucket capacity
#define WPB     8                // warps per block (256 threads)

// ---------------- HMMA GEMM tile constants ----------------
#define TM   128
#define KC   64
#define LDA  72
#define LDB  72
#define SM_AH 0
#define SM_AL (SM_AH + TM * LDA * 2)
#define SM_BH (SM_AL + TM * LDA * 2)
#define SM_BL (SM_BH + 64 * LDB * 2)
#define SM_SZ (SM_BL + 64 * LDB * 2)       // 55296

// layer-2 (K=64, TM=64) layout
#define SM2_AH 0
#define SM2_AL (SM2_AH + 64 * LDA * 2)
#define SM2_BH (SM2_AL + 64 * LDA * 2)
#define SM2_BL (SM2_BH + 64 * LDB * 2)
#define SM2_SZ (SM2_BL + 64 * LDB * 2)     // 36864

// ---------------- scratch (device globals; allocation-free) ----------------
__device__ int   g_cnt  [NN];      // zero at load; attn_l2 re-zeroes each run
__device__ int   g_csr  [(size_t)NN * CAP];
__device__ float g_h1   [(size_t)NN * HIDDIM];
__device__ float g_scs1 [(size_t)NN * H1];
__device__ float g_scd1 [(size_t)NN * H1];
__device__ float g_x2   [(size_t)NN * HIDDIM];
__device__ float g_h2   [(size_t)NN * OUTDIM];
__device__ float g_scs2 [NN];
__device__ float g_scd2 [NN];
// pre-split, pre-transposed W2: [n][k] u16 (bf16 bits); filled by gemm_l1 tail
__device__ __align__(16) unsigned short g_w2h[64 * 64];
__device__ __align__(16) unsigned short g_w2l[64 * 64];

// ---------------- generic helpers ----------------
__device__ __forceinline__ float lrelu(float v) {
    return v > 0.f ? v : NEG_SLOPE * v;
}
__device__ __forceinline__ uint32_t bf16x2_of(float v0, float v1) {
    uint32_t r;
    asm("cvt.rn.bf16x2.f32 %0, %1, %2;" : "=r"(r) : "f"(v1), "f"(v0));
    return r;
}
__device__ __forceinline__ float bf16lo_as_f32(uint32_t w) { return __uint_as_float(w << 16); }
__device__ __forceinline__ float bf16hi_as_f32(uint32_t w) { return __uint_as_float(w & 0xffff0000u); }
__device__ __forceinline__ uint32_t smem_u32(const void* p) {
    uint32_t a;
    asm("{ .reg .u64 t; cvta.to.shared.u64 t, %1; cvt.u32.u64 %0, t; }" : "=r"(a) : "l"(p));
    return a;
}
__device__ __forceinline__ void ldsm_x4(uint32_t* r, uint32_t addr) {
    asm volatile("ldmatrix.sync.aligned.m8n8.x4.shared.b16 {%0,%1,%2,%3}, [%4];"
                 : "=r"(r[0]), "=r"(r[1]), "=r"(r[2]), "=r"(r[3]) : "r"(addr));
}
__device__ __forceinline__ void mma16816(float* d, const uint32_t* a, const uint32_t* b) {
    asm volatile("mma.sync.aligned.m16n8k16.row.col.f32.bf16.bf16.f32 "
                 "{%0,%1,%2,%3}, {%4,%5,%6,%7}, {%8,%9}, {%0,%1,%2,%3};"
                 : "+f"(d[0]), "+f"(d[1]), "+f"(d[2]), "+f"(d[3])
                 : "r"(a[0]), "r"(a[1]), "r"(a[2]), "r"(a[3]), "r"(b[0]), "r"(b[1]));
}
__device__ __forceinline__ void cvt_store_pair(char* smem, int offH, int offL,
                                               uint32_t off, float4 v) {
    uint32_t h0 = bf16x2_of(v.x, v.y);
    uint32_t h1 = bf16x2_of(v.z, v.w);
    uint32_t l0 = bf16x2_of(v.x - bf16lo_as_f32(h0), v.y - bf16hi_as_f32(h0));
    uint32_t l1 = bf16x2_of(v.z - bf16lo_as_f32(h1), v.w - bf16hi_as_f32(h1));
    *reinterpret_cast<uint2*>(smem + offH + off) = make_uint2(h0, h1);
    *reinterpret_cast<uint2*>(smem + offL + off) = make_uint2(l0, l1);
}

// ------- layer-1 GEMM: HMMA split, TM=128, NH=8 fused scores ------------------
// tail blocks: [gemmBlocks, gemmBlocks+csrBlocks) build CSR; rest prep W2.
__global__ void __launch_bounds__(256)
gemm_l1(const float* __restrict__ A, const float* __restrict__ B,
        float* __restrict__ C, int nrows,
        const float* __restrict__ a_s, const float* __restrict__ a_d,
        float* __restrict__ scs, float* __restrict__ scd,
        int gemmBlocks, int csrBlocks,
        const int* __restrict__ ei, int* __restrict__ cnt, int* __restrict__ csr,
        const float* __restrict__ W2,
        unsigned short* __restrict__ w2h, unsigned short* __restrict__ w2l)
{
    if ((int)blockIdx.x >= gemmBlocks) {
        int tail = blockIdx.x - gemmBlocks;
        if (tail < csrBlocks) {
            // ---- CSR bucket build (overlapped) ----
            int e = tail * blockDim.x + threadIdx.x;
            if (e >= ETOT) return;
            int s, d;
            if (e < EE) { s = ei[e]; d = ei[EE + e]; }
            else        { s = d = e - EE; }
            int pos = atomicAdd(&cnt[d], 1);
            if (pos < CAP) csr[(size_t)d * CAP + pos] = s;
        } else {
            // ---- W2 split+transpose (overlapped; ready before gemm_l2) ----
            int j = (tail - csrBlocks) * blockDim.x + threadIdx.x;
            if (j >= 64 * 64) return;
            int k = j >> 6, n = j & 63;
            float w = W2[j];
            uint32_t hw = bf16x2_of(w, 0.f);
            uint32_t lw = bf16x2_of(w - bf16lo_as_f32(hw), 0.f);
            int dst = (n << 6) + k;                  // [n][k]
            w2h[dst] = (unsigned short)(hw & 0xffffu);
            w2l[dst] = (unsigned short)(lw & 0xffffu);
        }
        return;
    }

    extern __shared__ char smem[];
    const uint32_t sb = smem_u32(smem);
    const int t    = threadIdx.x;
    const int wid  = t >> 5;
    const int lane = t & 31;
    const int brow = blockIdx.x * TM;
    const int wm   = wid * 16;

    const int mat = lane >> 3;
    const int rin = lane & 7;
    const uint32_t aoffH = sb + SM_AH + (uint32_t)(((wm + (mat & 1) * 8 + rin) * LDA + (mat >> 1) * 8) * 2);
    const uint32_t aoffL = sb + SM_AL + (uint32_t)(((wm + (mat & 1) * 8 + rin) * LDA + (mat >> 1) * 8) * 2);
    const uint32_t boff  = (uint32_t)((((mat >> 1) * 8 + rin) * LDB + (mat & 1) * 8) * 2);

    float acc[8][4];
#pragma unroll
    for (int j = 0; j < 8; j++)
#pragma unroll
        for (int q = 0; q < 4; q++) acc[j][q] = 0.f;

#pragma unroll 1
    for (int c = 0; c < INDIM / KC; c++) {
        const int kk = c * KC;
#pragma unroll
        for (int i = 0; i < 8; i++) {
            int idx = t + 256 * i;
            int r   = idx >> 4;
            int k4  = idx & 15;
            int grow = brow + r;
            float4 v = (grow < nrows)
                ? *reinterpret_cast<const float4*>(&A[(size_t)grow * INDIM + kk + k4 * 4])
                : make_float4(0.f, 0.f, 0.f, 0.f);
            cvt_store_pair(smem, SM_AH, SM_AL, (uint32_t)((r * LDA + k4 * 4) * 2), v);
        }
#pragma unroll
        for (int i = 0; i < 16; i++) {
            int idx = t + 256 * i;
            int n   = idx & 63;
            int k   = idx >> 6;
            float w = B[(size_t)(kk + k) * 64 + n];
            uint32_t hw = bf16x2_of(w, 0.f);
            uint32_t lw = bf16x2_of(w - bf16lo_as_f32(hw), 0.f);
            uint32_t off = (uint32_t)((n * LDB + k) * 2);
            *reinterpret_cast<unsigned short*>(smem + SM_BH + off) = (unsigned short)(hw & 0xffffu);
            *reinterpret_cast<unsigned short*>(smem + SM_BL + off) = (unsigned short)(lw & 0xffffu);
        }
        __syncthreads();

#pragma unroll
        for (int k16 = 0; k16 < 4; k16++) {
            const uint32_t kb = (uint32_t)(k16 * 32);
            uint32_t ah[4], al[4];
            ldsm_x4(ah, aoffH + kb);
            ldsm_x4(al, aoffL + kb);
#pragma unroll
            for (int j2 = 0; j2 < 4; j2++) {
                uint32_t gb = (uint32_t)(j2 * 16 * LDB * 2) + kb;
                uint32_t bh[4], bl[4];
                ldsm_x4(bh, sb + SM_BH + boff + gb);
                ldsm_x4(bl, sb + SM_BL + boff + gb);
                mma16816(acc[j2 * 2 + 0], ah, bh);
                mma16816(acc[j2 * 2 + 0], ah, bl);
                mma16816(acc[j2 * 2 + 0], al, bh);
                mma16816(acc[j2 * 2 + 1], ah, bh + 2);
                mma16816(acc[j2 * 2 + 1], ah, bl + 2);
                mma16816(acc[j2 * 2 + 1], al, bh + 2);
            }
        }
        __syncthreads();
    }

    const int g  = lane >> 2;
    const int tg = lane & 3;
    const int row0 = brow + wm + g;
    const int row1 = row0 + 8;

#pragma unroll
    for (int j = 0; j < 8; j++) {
        int col = j * 8 + tg * 2;
        if (row0 < nrows)
            *reinterpret_cast<float2*>(&C[(size_t)row0 * 64 + col]) = make_float2(acc[j][0], acc[j][1]);
        if (row1 < nrows)
            *reinterpret_cast<float2*>(&C[(size_t)row1 * 64 + col]) = make_float2(acc[j][2], acc[j][3]);
    }

    float s0[8], d0[8], s1[8], d1[8];
#pragma unroll
    for (int j = 0; j < 8; j++) {
        float as0 = a_s[j * 8 + tg * 2], as1 = a_s[j * 8 + tg * 2 + 1];
        float ad0 = a_d[j * 8 + tg * 2], ad1 = a_d[j * 8 + tg * 2 + 1];
        s0[j] = acc[j][0] * as0 + acc[j][1] * as1;
        d0[j] = acc[j][0] * ad0 + acc[j][1] * ad1;
        s1[j] = acc[j][2] * as0 + acc[j][3] * as1;
        d1[j] = acc[j][2] * ad0 + acc[j][3] * ad1;
    }
#pragma unroll
    for (int o = 1; o <= 2; o <<= 1) {
#pragma unroll
        for (int j = 0; j < 8; j++) {
            s0[j] += __shfl_xor_sync(0xffffffffu, s0[j], o);
            d0[j] += __shfl_xor_sync(0xffffffffu, d0[j], o);
            s1[j] += __shfl_xor_sync(0xffffffffu, s1[j], o);
            d1[j] += __shfl_xor_sync(0xffffffffu, d1[j], o);
        }
    }
    if (tg == 0) {
        if (row0 < nrows) {
            float4* sp = reinterpret_cast<float4*>(&scs[(size_t)row0 * 8]);
            float4* dp = reinterpret_cast<float4*>(&scd[(size_t)row0 * 8]);
            sp[0] = make_float4(s0[0], s0[1], s0[2], s0[3]);
            sp[1] = make_float4(s0[4], s0[5], s0[6], s0[7]);
            dp[0] = make_float4(d0[0], d0[1], d0[2], d0[3]);
            dp[1] = make_float4(d0[4], d0[5], d0[6], d0[7]);
        }
        if (row1 < nrows) {
            float4* sp = reinterpret_cast<float4*>(&scs[(size_t)row1 * 8]);
            float4* dp = reinterpret_cast<float4*>(&scd[(size_t)row1 * 8]);
            sp[0] = make_float4(s1[0], s1[1], s1[2], s1[3]);
            sp[1] = make_float4(s1[4], s1[5], s1[6], s1[7]);
            dp[0] = make_float4(d1[0], d1[1], d1[2], d1[3]);
            dp[1] = make_float4(d1[4], d1[5], d1[6], d1[7]);
        }
    }
}

// ------- layer-2 GEMM: HMMA split, TM=64, split-N warps, NH=1 fused scores ----
// B fill: vector copy of pre-split W2 (prepped by gemm_l1 tail blocks).
__global__ void __launch_bounds__(256)
gemm_l2(const float* __restrict__ A,
        const unsigned short* __restrict__ w2h, const unsigned short* __restrict__ w2l,
        float* __restrict__ C, int nrows,
        const float* __restrict__ a_s, const float* __restrict__ a_d,
        float* __restrict__ scs, float* __restrict__ scd)
{
    extern __shared__ char smem[];
    __shared__ float ps[2][64], pd[2][64];
    const uint32_t sb = smem_u32(smem);
    const int t    = threadIdx.x;
    const int wid  = t >> 5;
    const int lane = t & 31;
    const int brow = blockIdx.x * 64;
    const int wm   = (wid >> 1) * 16;
    const int nh   = (wid & 1) * 32;

    const int mat = lane >> 3;
    const int rin = lane & 7;
    const uint32_t aoffH = sb + SM2_AH + (uint32_t)(((wm + (mat & 1) * 8 + rin) * LDA + (mat >> 1) * 8) * 2);
    const uint32_t aoffL = sb + SM2_AL + (uint32_t)(((wm + (mat & 1) * 8 + rin) * LDA + (mat >> 1) * 8) * 2);
    const uint32_t boff  = (uint32_t)(((nh + (mat >> 1) * 8 + rin) * LDB + (mat & 1) * 8) * 2);

    float acc[4][4];
#pragma unroll
    for (int j = 0; j < 4; j++)
#pragma unroll
        for (int q = 0; q < 4; q++) acc[j][q] = 0.f;

#pragma unroll
    for (int i = 0; i < 4; i++) {
        int idx = t + 256 * i;
        int r   = idx >> 4;
        int k4  = idx & 15;
        int grow = brow + r;
        float4 v = (grow < nrows)
            ? *reinterpret_cast<const float4*>(&A[(size_t)grow * 64 + k4 * 4])
            : make_float4(0.f, 0.f, 0.f, 0.f);
        cvt_store_pair(smem, SM2_AH, SM2_AL, (uint32_t)((r * LDA + k4 * 4) * 2), v);
    }
    {
        const uint4* srcH = reinterpret_cast<const uint4*>(w2h);
        const uint4* srcL = reinterpret_cast<const uint4*>(w2l);
#pragma unroll
        for (int i = 0; i < 2; i++) {
            int seg = t + 256 * i;
            int n   = seg >> 3;
            int ks  = seg & 7;
            uint32_t doff = (uint32_t)(n * (LDB * 2) + ks * 16);
            *reinterpret_cast<uint4*>(smem + SM2_BH + doff) = srcH[seg];
            *reinterpret_cast<uint4*>(smem + SM2_BL + doff) = srcL[seg];
        }
    }
    __syncthreads();

#pragma unroll
    for (int k16 = 0; k16 < 4; k16++) {
        const uint32_t kb = (uint32_t)(k16 * 32);
        uint32_t ah[4], al[4];
        ldsm_x4(ah, aoffH + kb);
        ldsm_x4(al, aoffL + kb);
#pragma unroll
        for (int j2 = 0; j2 < 2; j2++) {
            uint32_t gb = (uint32_t)(j2 * 16 * LDB * 2) + kb;
            uint32_t bh[4], bl[4];
            ldsm_x4(bh, sb + SM2_BH + boff + gb);
            ldsm_x4(bl, sb + SM2_BL + boff + gb);
            mma16816(acc[j2 * 2 + 0], ah, bh);
            mma16816(acc[j2 * 2 + 0], ah, bl);
            mma16816(acc[j2 * 2 + 0], al, bh);
            mma16816(acc[j2 * 2 + 1], ah, bh + 2);
            mma16816(acc[j2 * 2 + 1], ah, bl + 2);
            mma16816(acc[j2 * 2 + 1], al, bh + 2);
        }
    }

    const int g  = lane >> 2;
    const int tg = lane & 3;
    const int row0 = brow + wm + g;
    const int row1 = row0 + 8;

#pragma unroll
    for (int j = 0; j < 4; j++) {
        int col = nh + j * 8 + tg * 2;
        if (row0 < nrows)
            *reinterpret_cast<float2*>(&C[(size_t)row0 * 64 + col]) = make_float2(acc[j][0], acc[j][1]);
        if (row1 < nrows)
            *reinterpret_cast<float2*>(&C[(size_t)row1 * 64 + col]) = make_float2(acc[j][2], acc[j][3]);
    }

    float s0 = 0.f, d0 = 0.f, s1 = 0.f, d1 = 0.f;
#pragma unroll
    for (int j = 0; j < 4; j++) {
        int col = nh + j * 8 + tg * 2;
        float as0 = a_s[col], as1 = a_s[col + 1];
        float ad0 = a_d[col], ad1 = a_d[col + 1];
        s0 += acc[j][0] * as0 + acc[j][1] * as1;
        d0 += acc[j][0] * ad0 + acc[j][1] * ad1;
        s1 += acc[j][2] * as0 + acc[j][3] * as1;
        d1 += acc[j][2] * ad0 + acc[j][3] * ad1;
    }
#pragma unroll
    for (int o = 1; o <= 2; o <<= 1) {
        s0 += __shfl_xor_sync(0xffffffffu, s0, o);
        d0 += __shfl_xor_sync(0xffffffffu, d0, o);
        s1 += __shfl_xor_sync(0xffffffffu, s1, o);
        d1 += __shfl_xor_sync(0xffffffffu, d1, o);
    }
    const int half = wid & 1;
    if (tg == 0) {
        ps[half][wm + g]     = s0;
        pd[half][wm + g]     = d0;
        ps[half][wm + g + 8] = s1;
        pd[half][wm + g + 8] = d1;
    }
    __syncthreads();
    if (t < 64) {
        int grow = brow + t;
        if (grow < nrows) {
            scs[grow] = ps[0][t] + ps[1][t];
            scd[grow] = pd[0][t] + pd[1][t];
        }
    }
}

// ---------------- layer-1 attention (R10-measured form) -----------------------
__global__ void __launch_bounds__(256)
attn_l1(const int* __restrict__ cnt, const int* __restrict__ csr,
        const float* __restrict__ scs, const float* __restrict__ scd,
        const float* __restrict__ h, const float* __restrict__ b,
        float* __restrict__ x2)
{
    __shared__ int   sbuf[WPB][CAP];
    __shared__ float vbuf[WPB][CAP][8];

    const int warp = (blockIdx.x * blockDim.x + threadIdx.x) >> 5;
    const int w    = (threadIdx.x >> 5);
    const int lane = threadIdx.x & 31;
    if (warp >= NN) return;
    const int d   = warp;
    const int deg = min(cnt[d], CAP);
    const size_t base = (size_t)d * CAP;

    for (int e = lane; e < deg; e += 32) sbuf[w][e] = csr[base + e];
    __syncwarp();

    const int hh = lane & 7;
    const float sdh = scd[(size_t)d * 8 + hh];
    float s = 0.f;
    for (int e = (lane >> 3); e < deg; e += 4) {
        int src = sbuf[w][e];
        float ex = __expf(lrelu(scs[(size_t)src * 8 + hh] + sdh));
        vbuf[w][e][hh] = ex;
        s += ex;
    }
    s += __shfl_xor_sync(0xffffffffu, s, 8);
    s += __shfl_xor_sync(0xffffffffu, s, 16);
    float inv = 1.f / (s + 1e-16f);
    __syncwarp();

    const int hsel = lane >> 2;
    float ih = __shfl_sync(0xffffffffu, inv, hsel);

    float acc0 = 0.f, acc1 = 0.f;
#pragma unroll 4
    for (int e = 0; e < deg; e++) {
        int src = sbuf[w][e];
        float p = vbuf[w][e][hsel];
        float2 hv = *reinterpret_cast<const float2*>(h + (size_t)src * 64 + lane * 2);
        acc0 += hv.x * p;
        acc1 += hv.y * p;
    }

    const float2 bb = *reinterpret_cast<const float2*>(b + lane * 2);
    float v0 = acc0 * ih + bb.x;
    float v1 = acc1 * ih + bb.y;
    float2 o;
    o.x = v0 > 0.f ? v0 : expm1f(v0);
    o.y = v1 > 0.f ? v1 : expm1f(v1);
    *reinterpret_cast<float2*>(x2 + (size_t)d * 64 + lane * 2) = o;
}

// ---------------- layer-2 attention + bias + log_softmax + cnt reset ----------
__global__ void __launch_bounds__(256)
attn_l2(int* __restrict__ cnt, const int* __restrict__ csr,
        const float* __restrict__ scs, const float* __restrict__ scd,
        const float* __restrict__ h, const float* __restrict__ b,
        float* __restrict__ out)
{
    __shared__ int2 ebuf[WPB][CAP];

    const int warp = (blockIdx.x * blockDim.x + threadIdx.x) >> 5;
    const int w    = (threadIdx.x >> 5);
    const int lane = threadIdx.x & 31;
    if (warp >= NN) return;
    const int d   = warp;
    const int deg = min(cnt[d], CAP);
    const size_t base = (size_t)d * CAP;
    const float sdd = scd[d];

    // reset cnt for the next invocation (deg already read)
    if (lane == 0) cnt[d] = 0;

    float s = 0.f;
    for (int e = lane; e < deg; e += 32) {
        int src = csr[base + e];
        float ex = __expf(lrelu(scs[src] + sdd));
        ebuf[w][e] = make_int2(src, __float_as_int(ex));
        s += ex;
    }
#pragma unroll
    for (int o = 16; o > 0; o >>= 1) s += __shfl_xor_sync(0xffffffffu, s, o);
    float inv = 1.f / (s + 1e-16f);
    __syncwarp();

    float acc0 = 0.f, acc1 = 0.f;
#pragma unroll 4
    for (int e = 0; e < deg; e++) {
        int2 rec = ebuf[w][e];
        float p = __int_as_float(rec.y);
        float2 hv = *reinterpret_cast<const float2*>(h + (size_t)rec.x * 64 + lane * 2);
        acc0 += hv.x * p;
        acc1 += hv.y * p;
    }

    const float2 bb = *reinterpret_cast<const float2*>(b + lane * 2);
    float v0 = acc0 * inv + bb.x;
    float v1 = acc1 * inv + bb.y;

    float mm = fmaxf(v0, v1);
#pragma unroll
    for (int o = 16; o > 0; o >>= 1) mm = fmaxf(mm, __shfl_xor_sync(0xffffffffu, mm, o));
    float ss = __expf(v0 - mm) + __expf(v1 - mm);
#pragma unroll
    for (int o = 16; o > 0; o >>= 1) ss += __shfl_xor_sync(0xffffffffu, ss, o);
    float ls = mm + logf(ss);
    float2 o2;
    o2.x = v0 - ls;
    o2.y = v1 - ls;
    *reinterpret_cast<float2*>(out + (size_t)d * 64 + lane * 2) = o2;
}

// ---------------- launch ----------------
extern "C" void kernel_launch(void* const* d_in, const int* in_sizes, int n_in,
                              void* d_out, int out_size)
{
    const float* x      = (const float*)d_in[0];
    const int*   ei     = (const int*)  d_in[1];
    const float* W1     = (const float*)d_in[2];
    const float* a_src1 = (const float*)d_in[3];
    const float* a_dst1 = (const float*)d_in[4];
    const float* b1     = (const float*)d_in[5];
    const float* W2     = (const float*)d_in[6];
    const float* a_src2 = (const float*)d_in[7];
    const float* a_dst2 = (const float*)d_in[8];
    const float* b2     = (const float*)d_in[9];
    float* out = (float*)d_out;

    int   *p_cnt, *p_csr;
    float *p_h1, *p_scs1, *p_scd1, *p_x2;
    float *p_h2, *p_scs2, *p_scd2;
    unsigned short *p_w2h, *p_w2l;
    cudaGetSymbolAddress((void**)&p_cnt,  g_cnt);
    cudaGetSymbolAddress((void**)&p_csr,  g_csr);
    cudaGetSymbolAddress((void**)&p_h1,   g_h1);
    cudaGetSymbolAddress((void**)&p_scs1, g_scs1);
    cudaGetSymbolAddress((void**)&p_scd1, g_scd1);
    cudaGetSymbolAddress((void**)&p_x2,   g_x2);
    cudaGetSymbolAddress((void**)&p_h2,   g_h2);
    cudaGetSymbolAddress((void**)&p_scs2, g_scs2);
    cudaGetSymbolAddress((void**)&p_scd2, g_scd2);
    cudaGetSymbolAddress((void**)&p_w2h,  g_w2h);
    cudaGetSymbolAddress((void**)&p_w2l,  g_w2l);

    const int n = NN;
    const int warpBlocks  = (n * 32 + 255) / 256;
    const int gemm1Blocks = (n + TM - 1) / TM;        // 782
    const int csrBlocks   = (ETOT + 255) / 256;       // 6641
    const int w2Blocks    = (64 * 64 + 255) / 256;    // 16
    const int gemm2Blocks = (n + 63) / 64;            // 1563

    cudaFuncSetAttribute(gemm_l1, cudaFuncAttributeMaxDynamicSharedMemorySize, SM_SZ);
    cudaFuncSetAttribute(gemm_l2, cudaFuncAttributeMaxDynamicSharedMemorySize, SM2_SZ);

    // ---- layer 1 (gemm + fused scores + overlapped CSR build + W2 prep) ----
    gemm_l1<<<gemm1Blocks + csrBlocks + w2Blocks, 256, SM_SZ>>>(
        x, W1, p_h1, n, a_src1, a_dst1, p_scs1, p_scd1,
        gemm1Blocks, csrBlocks, ei, p_cnt, p_csr, W2, p_w2h, p_w2l);
    attn_l1<<<warpBlocks, 256>>>(p_cnt, p_csr, p_scs1, p_scd1, p_h1, b1, p_x2);

    // ---- layer 2 ----
    gemm_l2<<<gemm2Blocks, 256, SM2_SZ>>>(
        p_x2, p_w2h, p_w2l, p_h2, n, a_src2, a_dst2, p_scs2, p_scd2);
    attn_l2<<<warpBlocks, 256>>>(p_cnt, p_csr, p_scs2, p_scd2, p_h2, b2, out);
}

// round 16
// speedup vs baseline: 1.4413x; 1.4413x over previous
#include <cuda_runtime.h>
#include <cuda_bf16.h>
#include <math.h>
#include <stdint.h>

// ---------------- problem constants ----------------
#define NN      100000
#define EE      1600000
#define ETOT    (EE + NN)        // edges + self loops
#define INDIM   512
#define H1      8
#define HIDDIM  64
#define OUTDIM  64
#define NEG_SLOPE 0.2f
#define CAP     64               // per-node in-edge bucket capacity
#define WPB     8                // warps per block (256 threads)

// ---------------- HMMA GEMM tile constants ----------------
#define TM   128
#define KC   64
#define LDA  72
#define LDB  72
#define SM_AH 0
#define SM_AL (SM_AH + TM * LDA * 2)
#define SM_BH (SM_AL + TM * LDA * 2)
#define SM_BL (SM_BH + 64 * LDB * 2)
#define SM_SZ (SM_BL + 64 * LDB * 2)       // 55296

// layer-2 (K=64, TM=64) layout
#define SM2_AH 0
#define SM2_AL (SM2_AH + 64 * LDA * 2)
#define SM2_BH (SM2_AL + 64 * LDA * 2)
#define SM2_BL (SM2_BH + 64 * LDB * 2)
#define SM2_SZ (SM2_BL + 64 * LDB * 2)     // 36864

// ---------------- scratch (device globals; allocation-free) ----------------
__device__ int   g_cnt  [NN];
__device__ int   g_csr  [(size_t)NN * CAP];
__device__ float g_h1   [(size_t)NN * HIDDIM];
__device__ float g_scs1 [(size_t)NN * H1];
__device__ float g_scd1 [(size_t)NN * H1];
__device__ float g_x2   [(size_t)NN * HIDDIM];
__device__ float g_h2   [(size_t)NN * OUTDIM];
__device__ float g_scs2 [NN];
__device__ float g_scd2 [NN];
// pre-split, pre-transposed W2: [n][k] u16 (bf16 bits); filled by gemm_l1 tail
__device__ __align__(16) unsigned short g_w2h[64 * 64];
__device__ __align__(16) unsigned short g_w2l[64 * 64];

// ---------------- generic helpers ----------------
__device__ __forceinline__ float lrelu(float v) {
    return v > 0.f ? v : NEG_SLOPE * v;
}
__device__ __forceinline__ uint32_t bf16x2_of(float v0, float v1) {
    uint32_t r;
    asm("cvt.rn.bf16x2.f32 %0, %1, %2;" : "=r"(r) : "f"(v1), "f"(v0));
    return r;
}
__device__ __forceinline__ float bf16lo_as_f32(uint32_t w) { return __uint_as_float(w << 16); }
__device__ __forceinline__ float bf16hi_as_f32(uint32_t w) { return __uint_as_float(w & 0xffff0000u); }
__device__ __forceinline__ uint32_t smem_u32(const void* p) {
    uint32_t a;
    asm("{ .reg .u64 t; cvta.to.shared.u64 t, %1; cvt.u32.u64 %0, t; }" : "=r"(a) : "l"(p));
    return a;
}
__device__ __forceinline__ void ldsm_x4(uint32_t* r, uint32_t addr) {
    asm volatile("ldmatrix.sync.aligned.m8n8.x4.shared.b16 {%0,%1,%2,%3}, [%4];"
                 : "=r"(r[0]), "=r"(r[1]), "=r"(r[2]), "=r"(r[3]) : "r"(addr));
}
__device__ __forceinline__ void mma16816(float* d, const uint32_t* a, const uint32_t* b) {
    asm volatile("mma.sync.aligned.m16n8k16.row.col.f32.bf16.bf16.f32 "
                 "{%0,%1,%2,%3}, {%4,%5,%6,%7}, {%8,%9}, {%0,%1,%2,%3};"
                 : "+f"(d[0]), "+f"(d[1]), "+f"(d[2]), "+f"(d[3])
                 : "r"(a[0]), "r"(a[1]), "r"(a[2]), "r"(a[3]), "r"(b[0]), "r"(b[1]));
}
__device__ __forceinline__ void cvt_store_pair(char* smem, int offH, int offL,
                                               uint32_t off, float4 v) {
    uint32_t h0 = bf16x2_of(v.x, v.y);
    uint32_t h1 = bf16x2_of(v.z, v.w);
    uint32_t l0 = bf16x2_of(v.x - bf16lo_as_f32(h0), v.y - bf16hi_as_f32(h0));
    uint32_t l1 = bf16x2_of(v.z - bf16lo_as_f32(h1), v.w - bf16hi_as_f32(h1));
    *reinterpret_cast<uint2*>(smem + offH + off) = make_uint2(h0, h1);
    *reinterpret_cast<uint2*>(smem + offL + off) = make_uint2(l0, l1);
}

// ------- layer-1 GEMM: HMMA split, TM=128, NH=8 fused scores ------------------
// tail blocks: [gemmBlocks, gemmBlocks+csrBlocks) build CSR; rest prep W2.
__global__ void __launch_bounds__(256)
gemm_l1(const float* __restrict__ A, const float* __restrict__ B,
        float* __restrict__ C, int nrows,
        const float* __restrict__ a_s, const float* __restrict__ a_d,
        float* __restrict__ scs, float* __restrict__ scd,
        int gemmBlocks, int csrBlocks,
        const int* __restrict__ ei, int* __restrict__ cnt, int* __restrict__ csr,
        const float* __restrict__ W2,
        unsigned short* __restrict__ w2h, unsigned short* __restrict__ w2l)
{
    if ((int)blockIdx.x >= gemmBlocks) {
        int tail = blockIdx.x - gemmBlocks;
        if (tail < csrBlocks) {
            int e = tail * blockDim.x + threadIdx.x;
            if (e >= ETOT) return;
            int s, d;
            if (e < EE) { s = ei[e]; d = ei[EE + e]; }
            else        { s = d = e - EE; }
            int pos = atomicAdd(&cnt[d], 1);
            if (pos < CAP) csr[(size_t)d * CAP + pos] = s;
        } else {
            int j = (tail - csrBlocks) * blockDim.x + threadIdx.x;
            if (j >= 64 * 64) return;
            int k = j >> 6, n = j & 63;
            float w = W2[j];
            uint32_t hw = bf16x2_of(w, 0.f);
            uint32_t lw = bf16x2_of(w - bf16lo_as_f32(hw), 0.f);
            int dst = (n << 6) + k;                  // [n][k]
            w2h[dst] = (unsigned short)(hw & 0xffffu);
            w2l[dst] = (unsigned short)(lw & 0xffffu);
        }
        return;
    }

    extern __shared__ char smem[];
    const uint32_t sb = smem_u32(smem);
    const int t    = threadIdx.x;
    const int wid  = t >> 5;
    const int lane = t & 31;
    const int brow = blockIdx.x * TM;
    const int wm   = wid * 16;

    const int mat = lane >> 3;
    const int rin = lane & 7;
    const uint32_t aoffH = sb + SM_AH + (uint32_t)(((wm + (mat & 1) * 8 + rin) * LDA + (mat >> 1) * 8) * 2);
    const uint32_t aoffL = sb + SM_AL + (uint32_t)(((wm + (mat & 1) * 8 + rin) * LDA + (mat >> 1) * 8) * 2);
    const uint32_t boff  = (uint32_t)((((mat >> 1) * 8 + rin) * LDB + (mat & 1) * 8) * 2);

    float acc[8][4];
#pragma unroll
    for (int j = 0; j < 8; j++)
#pragma unroll
        for (int q = 0; q < 4; q++) acc[j][q] = 0.f;

#pragma unroll 1
    for (int c = 0; c < INDIM / KC; c++) {
        const int kk = c * KC;
#pragma unroll
        for (int i = 0; i < 8; i++) {
            int idx = t + 256 * i;
            int r   = idx >> 4;
            int k4  = idx & 15;
            int grow = brow + r;
            float4 v = (grow < nrows)
                ? *reinterpret_cast<const float4*>(&A[(size_t)grow * INDIM + kk + k4 * 4])
                : make_float4(0.f, 0.f, 0.f, 0.f);
            cvt_store_pair(smem, SM_AH, SM_AL, (uint32_t)((r * LDA + k4 * 4) * 2), v);
        }
#pragma unroll
        for (int i = 0; i < 16; i++) {
            int idx = t + 256 * i;
            int n   = idx & 63;
            int k   = idx >> 6;
            float w = B[(size_t)(kk + k) * 64 + n];
            uint32_t hw = bf16x2_of(w, 0.f);
            uint32_t lw = bf16x2_of(w - bf16lo_as_f32(hw), 0.f);
            uint32_t off = (uint32_t)((n * LDB + k) * 2);
            *reinterpret_cast<unsigned short*>(smem + SM_BH + off) = (unsigned short)(hw & 0xffffu);
            *reinterpret_cast<unsigned short*>(smem + SM_BL + off) = (unsigned short)(lw & 0xffffu);
        }
        __syncthreads();

#pragma unroll
        for (int k16 = 0; k16 < 4; k16++) {
            const uint32_t kb = (uint32_t)(k16 * 32);
            uint32_t ah[4], al[4];
            ldsm_x4(ah, aoffH + kb);
            ldsm_x4(al, aoffL + kb);
#pragma unroll
            for (int j2 = 0; j2 < 4; j2++) {
                uint32_t gb = (uint32_t)(j2 * 16 * LDB * 2) + kb;
                uint32_t bh[4], bl[4];
                ldsm_x4(bh, sb + SM_BH + boff + gb);
                ldsm_x4(bl, sb + SM_BL + boff + gb);
                mma16816(acc[j2 * 2 + 0], ah, bh);
                mma16816(acc[j2 * 2 + 0], ah, bl);
                mma16816(acc[j2 * 2 + 0], al, bh);
                mma16816(acc[j2 * 2 + 1], ah, bh + 2);
                mma16816(acc[j2 * 2 + 1], ah, bl + 2);
                mma16816(acc[j2 * 2 + 1], al, bh + 2);
            }
        }
        __syncthreads();
    }

    const int g  = lane >> 2;
    const int tg = lane & 3;
    const int row0 = brow + wm + g;
    const int row1 = row0 + 8;

#pragma unroll
    for (int j = 0; j < 8; j++) {
        int col = j * 8 + tg * 2;
        if (row0 < nrows)
            *reinterpret_cast<float2*>(&C[(size_t)row0 * 64 + col]) = make_float2(acc[j][0], acc[j][1]);
        if (row1 < nrows)
            *reinterpret_cast<float2*>(&C[(size_t)row1 * 64 + col]) = make_float2(acc[j][2], acc[j][3]);
    }

    float s0[8], d0[8], s1[8], d1[8];
#pragma unroll
    for (int j = 0; j < 8; j++) {
        float as0 = a_s[j * 8 + tg * 2], as1 = a_s[j * 8 + tg * 2 + 1];
        float ad0 = a_d[j * 8 + tg * 2], ad1 = a_d[j * 8 + tg * 2 + 1];
        s0[j] = acc[j][0] * as0 + acc[j][1] * as1;
        d0[j] = acc[j][0] * ad0 + acc[j][1] * ad1;
        s1[j] = acc[j][2] * as0 + acc[j][3] * as1;
        d1[j] = acc[j][2] * ad0 + acc[j][3] * ad1;
    }
#pragma unroll
    for (int o = 1; o <= 2; o <<= 1) {
#pragma unroll
        for (int j = 0; j < 8; j++) {
            s0[j] += __shfl_xor_sync(0xffffffffu, s0[j], o);
            d0[j] += __shfl_xor_sync(0xffffffffu, d0[j], o);
            s1[j] += __shfl_xor_sync(0xffffffffu, s1[j], o);
            d1[j] += __shfl_xor_sync(0xffffffffu, d1[j], o);
        }
    }
    if (tg == 0) {
        if (row0 < nrows) {
            float4* sp = reinterpret_cast<float4*>(&scs[(size_t)row0 * 8]);
            float4* dp = reinterpret_cast<float4*>(&scd[(size_t)row0 * 8]);
            sp[0] = make_float4(s0[0], s0[1], s0[2], s0[3]);
            sp[1] = make_float4(s0[4], s0[5], s0[6], s0[7]);
            dp[0] = make_float4(d0[0], d0[1], d0[2], d0[3]);
            dp[1] = make_float4(d0[4], d0[5], d0[6], d0[7]);
        }
        if (row1 < nrows) {
            float4* sp = reinterpret_cast<float4*>(&scs[(size_t)row1 * 8]);
            float4* dp = reinterpret_cast<float4*>(&scd[(size_t)row1 * 8]);
            sp[0] = make_float4(s1[0], s1[1], s1[2], s1[3]);
            sp[1] = make_float4(s1[4], s1[5], s1[6], s1[7]);
            dp[0] = make_float4(d1[0], d1[1], d1[2], d1[3]);
            dp[1] = make_float4(d1[4], d1[5], d1[6], d1[7]);
        }
    }
}

// ------- layer-2 GEMM: HMMA split, TM=64, split-N warps, NH=1 fused scores ----
__global__ void __launch_bounds__(256)
gemm_l2(const float* __restrict__ A,
        const unsigned short* __restrict__ w2h, const unsigned short* __restrict__ w2l,
        float* __restrict__ C, int nrows,
        const float* __restrict__ a_s, const float* __restrict__ a_d,
        float* __restrict__ scs, float* __restrict__ scd)
{
    extern __shared__ char smem[];
    __shared__ float ps[2][64], pd[2][64];
    const uint32_t sb = smem_u32(smem);
    const int t    = threadIdx.x;
    const int wid  = t >> 5;
    const int lane = t & 31;
    const int brow = blockIdx.x * 64;
    const int wm   = (wid >> 1) * 16;
    const int nh   = (wid & 1) * 32;

    const int mat = lane >> 3;
    const int rin = lane & 7;
    const uint32_t aoffH = sb + SM2_AH + (uint32_t)(((wm + (mat & 1) * 8 + rin) * LDA + (mat >> 1) * 8) * 2);
    const uint32_t aoffL = sb + SM2_AL + (uint32_t)(((wm + (mat & 1) * 8 + rin) * LDA + (mat >> 1) * 8) * 2);
    const uint32_t boff  = (uint32_t)(((nh + (mat >> 1) * 8 + rin) * LDB + (mat & 1) * 8) * 2);

    float acc[4][4];
#pragma unroll
    for (int j = 0; j < 4; j++)
#pragma unroll
        for (int q = 0; q < 4; q++) acc[j][q] = 0.f;

#pragma unroll
    for (int i = 0; i < 4; i++) {
        int idx = t + 256 * i;
        int r   = idx >> 4;
        int k4  = idx & 15;
        int grow = brow + r;
        float4 v = (grow < nrows)
            ? *reinterpret_cast<const float4*>(&A[(size_t)grow * 64 + k4 * 4])
            : make_float4(0.f, 0.f, 0.f, 0.f);
        cvt_store_pair(smem, SM2_AH, SM2_AL, (uint32_t)((r * LDA + k4 * 4) * 2), v);
    }
    {
        const uint4* srcH = reinterpret_cast<const uint4*>(w2h);
        const uint4* srcL = reinterpret_cast<const uint4*>(w2l);
#pragma unroll
        for (int i = 0; i < 2; i++) {
            int seg = t + 256 * i;
            int n   = seg >> 3;
            int ks  = seg & 7;
            uint32_t doff = (uint32_t)(n * (LDB * 2) + ks * 16);
            *reinterpret_cast<uint4*>(smem + SM2_BH + doff) = srcH[seg];
            *reinterpret_cast<uint4*>(smem + SM2_BL + doff) = srcL[seg];
        }
    }
    __syncthreads();

#pragma unroll
    for (int k16 = 0; k16 < 4; k16++) {
        const uint32_t kb = (uint32_t)(k16 * 32);
        uint32_t ah[4], al[4];
        ldsm_x4(ah, aoffH + kb);
        ldsm_x4(al, aoffL + kb);
#pragma unroll
        for (int j2 = 0; j2 < 2; j2++) {
            uint32_t gb = (uint32_t)(j2 * 16 * LDB * 2) + kb;
            uint32_t bh[4], bl[4];
            ldsm_x4(bh, sb + SM2_BH + boff + gb);
            ldsm_x4(bl, sb + SM2_BL + boff + gb);
            mma16816(acc[j2 * 2 + 0], ah, bh);
            mma16816(acc[j2 * 2 + 0], ah, bl);
            mma16816(acc[j2 * 2 + 0], al, bh);
            mma16816(acc[j2 * 2 + 1], ah, bh + 2);
            mma16816(acc[j2 * 2 + 1], ah, bl + 2);
            mma16816(acc[j2 * 2 + 1], al, bh + 2);
        }
    }

    const int g  = lane >> 2;
    const int tg = lane & 3;
    const int row0 = brow + wm + g;
    const int row1 = row0 + 8;

#pragma unroll
    for (int j = 0; j < 4; j++) {
        int col = nh + j * 8 + tg * 2;
        if (row0 < nrows)
            *reinterpret_cast<float2*>(&C[(size_t)row0 * 64 + col]) = make_float2(acc[j][0], acc[j][1]);
        if (row1 < nrows)
            *reinterpret_cast<float2*>(&C[(size_t)row1 * 64 + col]) = make_float2(acc[j][2], acc[j][3]);
    }

    float s0 = 0.f, d0 = 0.f, s1 = 0.f, d1 = 0.f;
#pragma unroll
    for (int j = 0; j < 4; j++) {
        int col = nh + j * 8 + tg * 2;
        float as0 = a_s[col], as1 = a_s[col + 1];
        float ad0 = a_d[col], ad1 = a_d[col + 1];
        s0 += acc[j][0] * as0 + acc[j][1] * as1;
        d0 += acc[j][0] * ad0 + acc[j][1] * ad1;
        s1 += acc[j][2] * as0 + acc[j][3] * as1;
        d1 += acc[j][2] * ad0 + acc[j][3] * ad1;
    }
#pragma unroll
    for (int o = 1; o <= 2; o <<= 1) {
        s0 += __shfl_xor_sync(0xffffffffu, s0, o);
        d0 += __shfl_xor_sync(0xffffffffu, d0, o);
        s1 += __shfl_xor_sync(0xffffffffu, s1, o);
        d1 += __shfl_xor_sync(0xffffffffu, d1, o);
    }
    const int half = wid & 1;
    if (tg == 0) {
        ps[half][wm + g]     = s0;
        pd[half][wm + g]     = d0;
        ps[half][wm + g + 8] = s1;
        pd[half][wm + g + 8] = d1;
    }
    __syncthreads();
    if (t < 64) {
        int grow = brow + t;
        if (grow < nrows) {
            scs[grow] = ps[0][t] + ps[1][t];
            scd[grow] = pd[0][t] + pd[1][t];
        }
    }
}

// ---------------- layer-1 attention (R10-measured form) -----------------------
__global__ void __launch_bounds__(256)
attn_l1(const int* __restrict__ cnt, const int* __restrict__ csr,
        const float* __restrict__ scs, const float* __restrict__ scd,
        const float* __restrict__ h, const float* __restrict__ b,
        float* __restrict__ x2)
{
    __shared__ int   sbuf[WPB][CAP];
    __shared__ float vbuf[WPB][CAP][8];

    const int warp = (blockIdx.x * blockDim.x + threadIdx.x) >> 5;
    const int w    = (threadIdx.x >> 5);
    const int lane = threadIdx.x & 31;
    if (warp >= NN) return;
    const int d   = warp;
    const int deg = min(cnt[d], CAP);
    const size_t base = (size_t)d * CAP;

    for (int e = lane; e < deg; e += 32) sbuf[w][e] = csr[base + e];
    __syncwarp();

    const int hh = lane & 7;
    const float sdh = scd[(size_t)d * 8 + hh];
    float s = 0.f;
    for (int e = (lane >> 3); e < deg; e += 4) {
        int src = sbuf[w][e];
        float ex = __expf(lrelu(scs[(size_t)src * 8 + hh] + sdh));
        vbuf[w][e][hh] = ex;
        s += ex;
    }
    s += __shfl_xor_sync(0xffffffffu, s, 8);
    s += __shfl_xor_sync(0xffffffffu, s, 16);
    float inv = 1.f / (s + 1e-16f);
    __syncwarp();

    const int hsel = lane >> 2;
    float ih = __shfl_sync(0xffffffffu, inv, hsel);

    float acc0 = 0.f, acc1 = 0.f;
#pragma unroll 4
    for (int e = 0; e < deg; e++) {
        int src = sbuf[w][e];
        float p = vbuf[w][e][hsel];
        float2 hv = *reinterpret_cast<const float2*>(h + (size_t)src * 64 + lane * 2);
        acc0 += hv.x * p;
        acc1 += hv.y * p;
    }

    const float2 bb = *reinterpret_cast<const float2*>(b + lane * 2);
    float v0 = acc0 * ih + bb.x;
    float v1 = acc1 * ih + bb.y;
    float2 o;
    o.x = v0 > 0.f ? v0 : expm1f(v0);
    o.y = v1 > 0.f ? v1 : expm1f(v1);
    *reinterpret_cast<float2*>(x2 + (size_t)d * 64 + lane * 2) = o;
}

// ---------------- layer-2 attention (R13-exact form) --------------------------
__global__ void __launch_bounds__(256)
attn_l2(const int* __restrict__ cnt, const int* __restrict__ csr,
        const float* __restrict__ scs, const float* __restrict__ scd,
        const float* __restrict__ h, const float* __restrict__ b,
        float* __restrict__ out)
{
    __shared__ int2 ebuf[WPB][CAP];

    const int warp = (blockIdx.x * blockDim.x + threadIdx.x) >> 5;
    const int w    = (threadIdx.x >> 5);
    const int lane = threadIdx.x & 31;
    if (warp >= NN) return;
    const int d   = warp;
    const int deg = min(cnt[d], CAP);
    const size_t base = (size_t)d * CAP;
    const float sdd = scd[d];

    float s = 0.f;
    for (int e = lane; e < deg; e += 32) {
        int src = csr[base + e];
        float ex = __expf(lrelu(scs[src] + sdd));
        ebuf[w][e] = make_int2(src, __float_as_int(ex));
        s += ex;
    }
#pragma unroll
    for (int o = 16; o > 0; o >>= 1) s += __shfl_xor_sync(0xffffffffu, s, o);
    float inv = 1.f / (s + 1e-16f);
    __syncwarp();

    float acc0 = 0.f, acc1 = 0.f;
#pragma unroll 4
    for (int e = 0; e < deg; e++) {
        int2 rec = ebuf[w][e];
        float p = __int_as_float(rec.y);
        float2 hv = *reinterpret_cast<const float2*>(h + (size_t)rec.x * 64 + lane * 2);
        acc0 += hv.x * p;
        acc1 += hv.y * p;
    }

    const float2 bb = *reinterpret_cast<const float2*>(b + lane * 2);
    float v0 = acc0 * inv + bb.x;
    float v1 = acc1 * inv + bb.y;

    float mm = fmaxf(v0, v1);
#pragma unroll
    for (int o = 16; o > 0; o >>= 1) mm = fmaxf(mm, __shfl_xor_sync(0xffffffffu, mm, o));
    float ss = __expf(v0 - mm) + __expf(v1 - mm);
#pragma unroll
    for (int o = 16; o > 0; o >>= 1) ss += __shfl_xor_sync(0xffffffffu, ss, o);
    float ls = mm + logf(ss);
    float2 o2;
    o2.x = v0 - ls;
    o2.y = v1 - ls;
    *reinterpret_cast<float2*>(out + (size_t)d * 64 + lane * 2) = o2;
}

// ---------------- launch ----------------
extern "C" void kernel_launch(void* const* d_in, const int* in_sizes, int n_in,
                              void* d_out, int out_size)
{
    const float* x      = (const float*)d_in[0];
    const int*   ei     = (const int*)  d_in[1];
    const float* W1     = (const float*)d_in[2];
    const float* a_src1 = (const float*)d_in[3];
    const float* a_dst1 = (const float*)d_in[4];
    const float* b1     = (const float*)d_in[5];
    const float* W2     = (const float*)d_in[6];
    const float* a_src2 = (const float*)d_in[7];
    const float* a_dst2 = (const float*)d_in[8];
    const float* b2     = (const float*)d_in[9];
    float* out = (float*)d_out;

    int   *p_cnt, *p_csr;
    float *p_h1, *p_scs1, *p_scd1, *p_x2;
    float *p_h2, *p_scs2, *p_scd2;
    unsigned short *p_w2h, *p_w2l;
    cudaGetSymbolAddress((void**)&p_cnt,  g_cnt);
    cudaGetSymbolAddress((void**)&p_csr,  g_csr);
    cudaGetSymbolAddress((void**)&p_h1,   g_h1);
    cudaGetSymbolAddress((void**)&p_scs1, g_scs1);
    cudaGetSymbolAddress((void**)&p_scd1, g_scd1);
    cudaGetSymbolAddress((void**)&p_x2,   g_x2);
    cudaGetSymbolAddress((void**)&p_h2,   g_h2);
    cudaGetSymbolAddress((void**)&p_scs2, g_scs2);
    cudaGetSymbolAddress((void**)&p_scd2, g_scd2);
    cudaGetSymbolAddress((void**)&p_w2h,  g_w2h);
    cudaGetSymbolAddress((void**)&p_w2l,  g_w2l);

    const int n = NN;
    const int warpBlocks  = (n * 32 + 255) / 256;
    const int gemm1Blocks = (n + TM - 1) / TM;        // 782
    const int csrBlocks   = (ETOT + 255) / 256;       // 6641
    const int w2Blocks    = (64 * 64 + 255) / 256;    // 16
    const int gemm2Blocks = (n + 63) / 64;            // 1563

    cudaFuncSetAttribute(gemm_l1, cudaFuncAttributeMaxDynamicSharedMemorySize, SM_SZ);
    cudaFuncSetAttribute(gemm_l2, cudaFuncAttributeMaxDynamicSharedMemorySize, SM2_SZ);

    // ---- layer 1 (gemm + fused scores + overlapped CSR build + W2 prep) ----
    cudaMemsetAsync(p_cnt, 0, (size_t)n * sizeof(int));
    gemm_l1<<<gemm1Blocks + csrBlocks + w2Blocks, 256, SM_SZ>>>(
        x, W1, p_h1, n, a_src1, a_dst1, p_scs1, p_scd1,
        gemm1Blocks, csrBlocks, ei, p_cnt, p_csr, W2, p_w2h, p_w2l);
    attn_l1<<<warpBlocks, 256>>>(p_cnt, p_csr, p_scs1, p_scd1, p_h1, b1, p_x2);

    // ---- layer 2 ----
    gemm_l2<<<gemm2Blocks, 256, SM2_SZ>>>(
        p_x2, p_w2h, p_w2l, p_h2, n, a_src2, a_dst2, p_scs2, p_scd2);
    attn_l2<<<warpBlocks, 256>>>(p_cnt, p_csr, p_scs2, p_scd2, p_h2, b2, out);
}